// round 15
// baseline (speedup 1.0000x reference)
#include <cuda_runtime.h>
#include <cuda_bf16.h>

#define BB 4096
#define TT 512
#define CH 8            // timesteps per chunk
#define NCH (TT / CH)   // 64 chunks
#define NB 8            // batches per CTA

typedef unsigned long long u64;
typedef unsigned int u32;

// ---------------- smem layout (per 256-thread CTA) ----------------
// Gate/W column order PERMUTED: n = j*4 + g  (unit-major; gates f,i,o,z)
#define W_HI   0                    // W bf16-hi [n=128][128B rows, swz] 16KB
#define W_LO   16384                // W bf16-lo                         16KB
#define A_HI   32768                // x tile hi [64 rows][128B, swz]     8KB
#define A_LO   40960                // x tile lo                          8KB
#define XF32   49152                // raw x staging [64 rows][64 f32]   16KB
#define RING   65536                // proj ring: 2 slots x [64][136] f32
#define RSLOT_F 8704                // ring slot size in FLOATS (64*136)
#define PROW   136
#define HSH_O  135168               // h bcast: 4 cons warps x 2 b x 2 buf x 32f
#define BIAS_O 139264               // bias [128] floats (permuted)
#define SM_TOT 139776

__device__ __forceinline__ u32 smem_u32(const void* p) {
    u32 a;
    asm("{ .reg .u64 t; cvta.to.shared.u64 t, %1; cvt.u32.u64 %0, t; }"
        : "=r"(a) : "l"(p));
    return a;
}
__device__ __forceinline__ u32 swz(u32 off) { return off ^ ((off >> 3) & 0x70); }
__device__ __forceinline__ void cp16(u32 dst, const void* src) {
    asm volatile("cp.async.ca.shared.global [%0], [%1], 16;"
                 :: "r"(dst), "l"(src) : "memory");
}
#define BAR_SYNC(id, cnt)   asm volatile("bar.sync %0, %1;"   :: "r"(id), "r"(cnt) : "memory")
#define BAR_ARRIVE(id, cnt) asm volatile("bar.arrive %0, %1;" :: "r"(id), "r"(cnt) : "memory")

// ---- packed fp32x2 ----
__device__ __forceinline__ u64 pk2(float lo, float hi) {
    u64 r; asm("mov.b64 %0, {%1,%2};" : "=l"(r) : "f"(lo), "f"(hi)); return r;
}
__device__ __forceinline__ void upk2(u64 v, float &lo, float &hi) {
    asm("mov.b64 {%0,%1}, %2;" : "=f"(lo), "=f"(hi) : "l"(v));
}
__device__ __forceinline__ void fma2(u64 &acc, u64 a, u64 b) {
    asm("fma.rn.f32x2 %0, %1, %2, %0;" : "+l"(acc) : "l"(a), "l"(b));
}

// ---- HMMA ----
__device__ __forceinline__ void ldsm4(u32 &r0, u32 &r1, u32 &r2, u32 &r3, u32 a) {
    asm volatile("ldmatrix.sync.aligned.m8n8.x4.shared.b16 {%0,%1,%2,%3}, [%4];"
                 : "=r"(r0), "=r"(r1), "=r"(r2), "=r"(r3) : "r"(a));
}
__device__ __forceinline__ void mma16816(float* c, const u32* a, u32 b0, u32 b1) {
    asm volatile(
        "mma.sync.aligned.m16n8k16.row.col.f32.bf16.bf16.f32 "
        "{%0,%1,%2,%3}, {%4,%5,%6,%7}, {%8,%9}, {%0,%1,%2,%3};"
        : "+f"(c[0]), "+f"(c[1]), "+f"(c[2]), "+f"(c[3])
        : "r"(a[0]), "r"(a[1]), "r"(a[2]), "r"(a[3]), "r"(b0), "r"(b1));
}

// =====================================================================
// R14: R13 warp-specialized kernel with the ring-slot index bug fixed
// (RSLOT was bytes, used as float offset -> OOB smem). Warps 0-3 produce
// proj chunks into a depth-2 ring; warps 4-7 scan continuously.
// =====================================================================
__global__ void __launch_bounds__(256, 1) fused_kernel(
    const float* __restrict__ x,
    const float* __restrict__ wf, const float* __restrict__ wfb,
    const float* __restrict__ wi, const float* __restrict__ wib,
    const float* __restrict__ wo, const float* __restrict__ wob,
    const float* __restrict__ wz, const float* __restrict__ wzb,
    const float* __restrict__ rf, const float* __restrict__ ri,
    const float* __restrict__ ro, const float* __restrict__ rz,
    const void*  __restrict__ tick, const float* __restrict__ emb,
    const float* __restrict__ fcw, const float* __restrict__ fcb,
    float* __restrict__ out)
{
    extern __shared__ __align__(1024) char sm[];
    const int tid = threadIdx.x;
    const int w = tid >> 5, lane = tid & 31;
    const u32 sb = smem_u32(sm);
    const int bg = blockIdx.x;

    // ---- stage W hi/lo (PERMUTED n = j*4+g) + bias, all 256 threads ----
    for (int i = tid; i < 4096; i += 256) {          // (n, k-pair)
        int n = i >> 5, kp = i & 31;
        int j = n >> 2, g = n & 3;
        const float* wp = (g == 0) ? wf : (g == 1) ? wi : (g == 2) ? wo : wz;
        float a = wp[j * 64 + kp * 2], b = wp[j * 64 + kp * 2 + 1];
        __nv_bfloat162 h2 = __floats2bfloat162_rn(a, b);
        float ha = __bfloat162float(h2.x), hb = __bfloat162float(h2.y);
        __nv_bfloat162 l2 = __floats2bfloat162_rn(a - ha, b - hb);
        u32 off = swz((u32)(n * 128 + kp * 4));
        *(u32*)(sm + W_HI + off) = *(u32*)&h2;
        *(u32*)(sm + W_LO + off) = *(u32*)&l2;
    }
    if (tid < 128) {                                 // permuted bias
        int j = tid >> 2, g = tid & 3;
        const float* bb = (g == 0) ? wfb : (g == 1) ? wib : (g == 2) ? wob : wzb;
        ((float*)(sm + BIAS_O))[tid] = bb[j];
    }
    __syncthreads();

    float* ringf = (float*)(sm + RING);
    const float* bsm = (const float*)(sm + BIAS_O);

    if (w < 4) {
        // ================= PRODUCER (warps 0-3, 128 threads) =================
        const int ptid = tid;                        // 0..127
        auto ldx = [&](int c) {                      // 1024 float4, 8/thread
            #pragma unroll
            for (int q = 0; q < 8; ++q) {
                int idx = q * 128 + ptid;
                int row = idx >> 4, c4 = idx & 15;   // row = bi*8 + step
                size_t gi = ((size_t)(bg * NB + (row >> 3)) * TT + c * CH + (row & 7)) * 16 + c4;
                cp16(sb + XF32 + idx * 16, (const float4*)x + gi);
            }
            asm volatile("cp.async.commit_group;" ::: "memory");
        };
        ldx(0);

        const int arow_l = lane & 15, acol_l = (lane >> 4) * 16;
        const int brow_l = (lane & 7) + ((lane >> 4) << 3);
        const int bcol_l = ((lane >> 3) & 1) * 16;

        for (int ck = 0; ck < NCH; ++ck) {
            const int slot = ck & 1;
            asm volatile("cp.async.wait_group 0;" ::: "memory");
            BAR_SYNC(5, 128);                        // prev HMMA done reading A
            // convert XF32 -> A_HI/A_LO (bf16 hi/lo, swz)
            #pragma unroll
            for (int q = 0; q < 8; ++q) {
                int idx = q * 128 + ptid;
                float4 v = *(const float4*)(sm + XF32 + idx * 16);
                int row = idx >> 4, c4 = idx & 15;
                __nv_bfloat162 h0 = __floats2bfloat162_rn(v.x, v.y);
                __nv_bfloat162 h1 = __floats2bfloat162_rn(v.z, v.w);
                float r0 = v.x - __bfloat162float(h0.x);
                float r1 = v.y - __bfloat162float(h0.y);
                float r2 = v.z - __bfloat162float(h1.x);
                float r3 = v.w - __bfloat162float(h1.y);
                __nv_bfloat162 l0 = __floats2bfloat162_rn(r0, r1);
                __nv_bfloat162 l1 = __floats2bfloat162_rn(r2, r3);
                u32 off = swz((u32)(row * 128 + c4 * 8));
                *(u64*)(sm + A_HI + off) = (u64)(*(u32*)&h0) | ((u64)(*(u32*)&h1) << 32);
                *(u64*)(sm + A_LO + off) = (u64)(*(u32*)&l0) | ((u64)(*(u32*)&l1) << 32);
            }
            BAR_SYNC(5, 128);                        // A ready, XF32 free
            if (ck + 1 < NCH) ldx(ck + 1);

            if (ck >= 2) BAR_SYNC(3 + slot, 256);    // wait ring slot empty

            // HMMA: this warp -> cols w*32..+31, rows 64 in 4 m16 groups
            float* pr = ringf + (size_t)slot * RSLOT_F;
            #pragma unroll
            for (int gh = 0; gh < 4; ++gh) {
                float acc[4][4];
                #pragma unroll
                for (int nt = 0; nt < 4; ++nt)
                    #pragma unroll
                    for (int q = 0; q < 4; ++q) acc[nt][q] = 0.f;
                #pragma unroll
                for (int s = 0; s < 4; ++s) {
                    u32 ah[4], al[4];
                    u32 aoff = swz((u32)((gh * 16 + arow_l) * 128 + s * 32 + acol_l));
                    ldsm4(ah[0], ah[1], ah[2], ah[3], sb + A_HI + aoff);
                    ldsm4(al[0], al[1], al[2], al[3], sb + A_LO + aoff);
                    #pragma unroll
                    for (int np = 0; np < 2; ++np) {
                        u32 bh[4], bl[4];
                        u32 boff = swz((u32)((w * 32 + np * 16 + brow_l) * 128 + s * 32 + bcol_l));
                        ldsm4(bh[0], bh[1], bh[2], bh[3], sb + W_HI + boff);
                        ldsm4(bl[0], bl[1], bl[2], bl[3], sb + W_LO + boff);
                        #pragma unroll
                        for (int nh = 0; nh < 2; ++nh) {
                            float* a5 = acc[np * 2 + nh];
                            mma16816(a5, ah, bh[nh * 2], bh[nh * 2 + 1]);
                            mma16816(a5, al, bh[nh * 2], bh[nh * 2 + 1]);
                            mma16816(a5, ah, bl[nh * 2], bl[nh * 2 + 1]);
                        }
                    }
                }
                int r0 = gh * 16 + (lane >> 2);
                #pragma unroll
                for (int nt = 0; nt < 4; ++nt) {
                    int col = w * 32 + nt * 8 + (lane & 3) * 2;
                    float b0v = bsm[col], b1v = bsm[col + 1];
                    *(float2*)&pr[r0 * PROW + col] =
                        make_float2(acc[nt][0] + b0v, acc[nt][1] + b1v);
                    *(float2*)&pr[(r0 + 8) * PROW + col] =
                        make_float2(acc[nt][2] + b0v, acc[nt][3] + b1v);
                }
            }
            BAR_ARRIVE(1 + slot, 256);               // ring slot full
        }
    } else {
        // ================= CONSUMER (warps 4-7, scan) =================
        const int cw = w - 4;
        const int b0 = bg * NB + cw * 2;             // this warp's two batches

        // recurrent weights, register-resident (row j = lane), shared A/B
        u64 Rf[16], Ri[16], Ro[16], Rz[16];
        {
            const u64* pf = (const u64*)(rf + lane * 32);
            const u64* pi = (const u64*)(ri + lane * 32);
            const u64* po = (const u64*)(ro + lane * 32);
            const u64* pz = (const u64*)(rz + lane * 32);
            #pragma unroll
            for (int k = 0; k < 16; ++k) {
                Rf[k] = pf[k]; Ri[k] = pi[k]; Ro[k] = po[k]; Rz[k] = pz[k];
            }
        }
        float hA = 0.f, cA = 0.f, nA = 0.f;
        float hB = 0.f, cB = 0.f, nB = 0.f;
        float* hshw = (float*)(sm + HSH_O) + cw * 128;   // [batch][buf][32]

        for (int ck = 0; ck < NCH; ++ck) {
            const int slot = ck & 1;
            BAR_SYNC(1 + slot, 256);                 // wait ring slot full
            const float* gpA = ringf + (size_t)slot * RSLOT_F
                             + (size_t)(cw * 2) * CH * PROW + lane * 4;
            const float* gpB = gpA + (size_t)CH * PROW;
            #pragma unroll
            for (int s = 0; s < CH; ++s) {
                const int buf = s & 1;
                float4 gA = *(const float4*)(gpA + s * PROW);  // f,i,o,z
                float4 gB = *(const float4*)(gpB + s * PROW);

                hshw[buf * 32 + lane] = hA;
                hshw[64 + buf * 32 + lane] = hB;
                __syncwarp();
                const u64* hpA = (const u64*)(hshw + buf * 32);
                const u64* hpB = (const u64*)(hshw + 64 + buf * 32);

                u64 afA = pk2(gA.x, 0.f), aiA = pk2(gA.y, 0.f);
                u64 aoA = pk2(gA.z, 0.f), azA = pk2(gA.w, 0.f);
                u64 afB = pk2(gB.x, 0.f), aiB = pk2(gB.y, 0.f);
                u64 aoB = pk2(gB.z, 0.f), azB = pk2(gB.w, 0.f);
                #pragma unroll
                for (int k = 0; k < 16; ++k) {
                    u64 hhA = hpA[k], hhB = hpB[k];
                    fma2(afA, Rf[k], hhA);  fma2(afB, Rf[k], hhB);
                    fma2(aiA, Ri[k], hhA);  fma2(aiB, Ri[k], hhB);
                    fma2(aoA, Ro[k], hhA);  fma2(aoB, Ro[k], hhB);
                    fma2(azA, Rz[k], hhA);  fma2(azB, Rz[k], hhB);
                }
                float lo, hi;
                upk2(afA, lo, hi); float fTA = lo + hi;
                upk2(aiA, lo, hi); float iTA = lo + hi;
                upk2(aoA, lo, hi); float oTA = lo + hi;
                upk2(azA, lo, hi); float zTA = lo + hi;
                upk2(afB, lo, hi); float fTB = lo + hi;
                upk2(aiB, lo, hi); float iTB = lo + hi;
                upk2(aoB, lo, hi); float oTB = lo + hi;
                upk2(azB, lo, hi); float zTB = lo + hi;

                {   // batch A epilogue
                    float fh = __expf(fminf(fTA, 10.f));
                    float ih = __expf(fminf(iTA, 10.f));
                    float rden = __fdividef(1.f, fh + ih + 1e-8f);
                    float f  = fh * rden;
                    float ii = ih * rden;
                    float o  = __fdividef(1.f, 1.f + __expf(-oTA));
                    float za = fabsf(zTA);
                    float e2 = __expf(-2.f * za);
                    float z  = copysignf(__fdividef(1.f - e2, 1.f + e2), zTA);
                    cA = f * cA + ii * z;
                    nA = f * nA + ii;
                    hA = o * __fdividef(cA, nA + 1e-8f);
                }
                {   // batch B epilogue
                    float fh = __expf(fminf(fTB, 10.f));
                    float ih = __expf(fminf(iTB, 10.f));
                    float rden = __fdividef(1.f, fh + ih + 1e-8f);
                    float f  = fh * rden;
                    float ii = ih * rden;
                    float o  = __fdividef(1.f, 1.f + __expf(-oTB));
                    float za = fabsf(zTB);
                    float e2 = __expf(-2.f * za);
                    float z  = copysignf(__fdividef(1.f - e2, 1.f + e2), zTB);
                    cB = f * cB + ii * z;
                    nB = f * nB + ii;
                    hB = o * __fdividef(cB, nB + 1e-8f);
                }
            }
            BAR_ARRIVE(3 + slot, 256);               // ring slot empty
        }

        // ---- head: tanh(fc_w . [h, emb[ticker]] + fc_b), both batches ----
        const int* p32 = (const int*)tick;
        bool is64 = ((p32[1] | p32[3] | p32[5] | p32[7] |
                      p32[9] | p32[11] | p32[13] | p32[15]) == 0);
        long long idA = is64 ? ((const long long*)tick)[b0]     : (long long)p32[b0];
        long long idB = is64 ? ((const long long*)tick)[b0 + 1] : (long long)p32[b0 + 1];
        float vA = fcw[lane] * hA;
        float vB = fcw[lane] * hB;
        if (lane < 8) {
            vA += fcw[32 + lane] * emb[idA * 8 + lane];
            vB += fcw[32 + lane] * emb[idB * 8 + lane];
        }
        #pragma unroll
        for (int off = 16; off; off >>= 1) {
            vA += __shfl_xor_sync(0xffffffffu, vA, off);
            vB += __shfl_xor_sync(0xffffffffu, vB, off);
        }
        if (lane == 0) {
            out[b0]     = tanhf(vA + fcb[0]);
            out[b0 + 1] = tanhf(vB + fcb[0]);
        }
    }
}

// =====================================================================
extern "C" void kernel_launch(void* const* d_in, const int* in_sizes, int n_in,
                              void* d_out, int out_size) {
    const float* x   = (const float*)d_in[0];
    const void*  tid = d_in[1];
    const float* wf  = (const float*)d_in[2];
    const float* wfb = (const float*)d_in[3];
    const float* wi  = (const float*)d_in[4];
    const float* wib = (const float*)d_in[5];
    const float* wo  = (const float*)d_in[6];
    const float* wob = (const float*)d_in[7];
    const float* wz  = (const float*)d_in[8];
    const float* wzb = (const float*)d_in[9];
    const float* rf  = (const float*)d_in[10];
    const float* ri  = (const float*)d_in[11];
    const float* ro  = (const float*)d_in[12];
    const float* rz  = (const float*)d_in[13];
    const float* emb = (const float*)d_in[14];
    const float* fcw = (const float*)d_in[15];
    const float* fcb = (const float*)d_in[16];
    float* out = (float*)d_out;

    cudaFuncSetAttribute(fused_kernel,
                         cudaFuncAttributeMaxDynamicSharedMemorySize, SM_TOT);

    fused_kernel<<<BB / NB, 256, SM_TOT>>>(
        x, wf, wfb, wi, wib, wo, wob, wz, wzb,
        rf, ri, ro, rz, tid, emb, fcw, fcb, out);
}

// round 16
// speedup vs baseline: 1.0578x; 1.0578x over previous
#include <cuda_runtime.h>
#include <cuda_bf16.h>

#define BB 4096
#define TT 512
#define CH 16           // timesteps per chunk
#define NCH (TT / CH)   // 32 chunks
#define NB 4            // batches per CTA (1 per warp)

typedef unsigned long long u64;
typedef unsigned int u32;

// ---------------- smem layout (per 128-thread CTA, 101888 B) ----------------
// Gate/W column order PERMUTED: n = j*4 + g (unit-major; gates f,i,o,z)
#define W_HI   0                    // W bf16-hi [n=128][128B rows, swz] 16KB
#define W_LO   16384                // W bf16-lo                         16KB
#define A_HI   32768                // x tile hi [64 rows][128B, swz]     8KB
#define A_LO   40960                // x tile lo                          8KB
#define PROJ_O 49152                // proj chunk [64 rows][136 f32]  34816B
#define PROW   136
#define XF32   83968                // raw x staging [64 rows][64 f32]  16KB
#define HSH_O  100352               // h bcast: 4 warps x 2 buf x 32 f   1KB
#define BIAS_O 101376               // bias [128] f32 (permuted)        512B
#define SM_TOT 101888

__device__ __forceinline__ u32 smem_u32(const void* p) {
    u32 a;
    asm("{ .reg .u64 t; cvta.to.shared.u64 t, %1; cvt.u32.u64 %0, t; }"
        : "=r"(a) : "l"(p));
    return a;
}
__device__ __forceinline__ u32 swz(u32 off) { return off ^ ((off >> 3) & 0x70); }
__device__ __forceinline__ void cp16(u32 dst, const void* src) {
    asm volatile("cp.async.ca.shared.global [%0], [%1], 16;"
                 :: "r"(dst), "l"(src) : "memory");
}

// ---- packed fp32x2 ----
__device__ __forceinline__ u64 pk2(float lo, float hi) {
    u64 r; asm("mov.b64 %0, {%1,%2};" : "=l"(r) : "f"(lo), "f"(hi)); return r;
}
__device__ __forceinline__ void upk2(u64 v, float &lo, float &hi) {
    asm("mov.b64 {%0,%1}, %2;" : "=f"(lo), "=f"(hi) : "l"(v));
}
__device__ __forceinline__ void fma2(u64 &acc, u64 a, u64 b) {
    asm("fma.rn.f32x2 %0, %1, %2, %0;" : "+l"(acc) : "l"(a), "l"(b));
}
__device__ __forceinline__ float tanh_hw(float x) {
    float r; asm("tanh.approx.f32 %0, %1;" : "=f"(r) : "f"(x)); return r;
}

// ---- HMMA ----
__device__ __forceinline__ void ldsm4(u32 &r0, u32 &r1, u32 &r2, u32 &r3, u32 a) {
    asm volatile("ldmatrix.sync.aligned.m8n8.x4.shared.b16 {%0,%1,%2,%3}, [%4];"
                 : "=r"(r0), "=r"(r1), "=r"(r2), "=r"(r3) : "r"(a));
}
__device__ __forceinline__ void mma16816(float* c, const u32* a, u32 b0, u32 b1) {
    asm volatile(
        "mma.sync.aligned.m16n8k16.row.col.f32.bf16.bf16.f32 "
        "{%0,%1,%2,%3}, {%4,%5,%6,%7}, {%8,%9}, {%0,%1,%2,%3};"
        : "+f"(c[0]), "+f"(c[1]), "+f"(c[2]), "+f"(c[3])
        : "r"(a[0]), "r"(a[1]), "r"(a[2]), "r"(a[3]), "r"(b0), "r"(b1));
}

// =====================================================================
// R16 = R9 champion (NB=4, CH=16, 2 CTAs/SM) + unit-major gates
// (1 LDS.128/step), tanh.approx for z, cp.async x staging (reg relief).
// =====================================================================
__global__ void __launch_bounds__(128, 2) fused_kernel(
    const float* __restrict__ x,
    const float* __restrict__ wf, const float* __restrict__ wfb,
    const float* __restrict__ wi, const float* __restrict__ wib,
    const float* __restrict__ wo, const float* __restrict__ wob,
    const float* __restrict__ wz, const float* __restrict__ wzb,
    const float* __restrict__ rf, const float* __restrict__ ri,
    const float* __restrict__ ro, const float* __restrict__ rz,
    const void*  __restrict__ tick, const float* __restrict__ emb,
    const float* __restrict__ fcw, const float* __restrict__ fcb,
    float* __restrict__ out)
{
    extern __shared__ __align__(1024) char sm[];
    const int tid = threadIdx.x;
    const int w = tid >> 5, lane = tid & 31;
    const u32 sb = smem_u32(sm);
    const int bg = blockIdx.x;
    const int batch = bg * NB + w;

    // ---- stage W hi/lo, PERMUTED rows n = j*4+g ----
    for (int i = tid; i < 4096; i += 128) {          // (n, k-pair)
        int n = i >> 5, kp = i & 31;
        int j = n >> 2, g = n & 3;
        const float* wp = (g == 0) ? wf : (g == 1) ? wi : (g == 2) ? wo : wz;
        float a = wp[j * 64 + kp * 2], b = wp[j * 64 + kp * 2 + 1];
        __nv_bfloat162 h2 = __floats2bfloat162_rn(a, b);
        float ha = __bfloat162float(h2.x), hb = __bfloat162float(h2.y);
        __nv_bfloat162 l2 = __floats2bfloat162_rn(a - ha, b - hb);
        u32 off = swz((u32)(n * 128 + kp * 4));
        *(u32*)(sm + W_HI + off) = *(u32*)&h2;
        *(u32*)(sm + W_LO + off) = *(u32*)&l2;
    }
    if (tid < 128) {                                 // permuted bias
        int j = tid >> 2, g = tid & 3;
        const float* bb = (g == 0) ? wfb : (g == 1) ? wib : (g == 2) ? wob : wzb;
        ((float*)(sm + BIAS_O))[tid] = bb[j];
    }

    // ---- x staging via cp.async: 4 batches x 16 steps x 64 f = 1024 f4 ----
    auto ldx = [&](int c) {
        #pragma unroll
        for (int q = 0; q < 8; ++q) {
            int idx = q * 128 + tid;
            int row = idx >> 4, c4 = idx & 15;       // row = bi*16 + step
            size_t gi = ((size_t)(bg * NB + (row >> 4)) * TT + c * CH + (row & 15)) * 16 + c4;
            cp16(sb + XF32 + idx * 16, (const float4*)x + gi);
        }
        asm volatile("cp.async.commit_group;" ::: "memory");
    };
    ldx(0);
    __syncthreads();                                 // W/bias staged

    // ---- recurrent weights, register-resident (row j = lane) ----
    u64 Rf[16], Ri[16], Ro[16], Rz[16];
    {
        const u64* pf = (const u64*)(rf + lane * 32);
        const u64* pi = (const u64*)(ri + lane * 32);
        const u64* po = (const u64*)(ro + lane * 32);
        const u64* pz = (const u64*)(rz + lane * 32);
        #pragma unroll
        for (int k = 0; k < 16; ++k) {
            Rf[k] = pf[k]; Ri[k] = pi[k]; Ro[k] = po[k]; Rz[k] = pz[k];
        }
    }

    float h = 0.f, cst = 0.f, nst = 0.f;
    float* projf = (float*)(sm + PROJ_O);
    float* hshw  = (float*)(sm + HSH_O) + w * 64;   // 2 bufs x 32
    const float* bsm = (const float*)(sm + BIAS_O);

    const int arow_l = lane & 15, acol_l = (lane >> 4) * 16;
    const int brow_l = (lane & 7) + ((lane >> 4) << 3);
    const int bcol_l = ((lane >> 3) & 1) * 16;

    for (int ck = 0; ck < NCH; ++ck) {
        asm volatile("cp.async.wait_group 0;" ::: "memory");
        __syncthreads();                 // x arrived; prev chunk fully consumed

        // ---- convert x fp32 smem -> bf16 hi/lo swz smem (64 rows) ----
        #pragma unroll
        for (int q = 0; q < 8; ++q) {
            int idx = q * 128 + tid;
            float4 v = *(const float4*)(sm + XF32 + idx * 16);
            int row = idx >> 4, c4 = idx & 15;
            __nv_bfloat162 h0 = __floats2bfloat162_rn(v.x, v.y);
            __nv_bfloat162 h1 = __floats2bfloat162_rn(v.z, v.w);
            float r0 = v.x - __bfloat162float(h0.x);
            float r1 = v.y - __bfloat162float(h0.y);
            float r2 = v.z - __bfloat162float(h1.x);
            float r3 = v.w - __bfloat162float(h1.y);
            __nv_bfloat162 l0 = __floats2bfloat162_rn(r0, r1);
            __nv_bfloat162 l1 = __floats2bfloat162_rn(r2, r3);
            u32 off = swz((u32)(row * 128 + c4 * 8));
            *(u64*)(sm + A_HI + off) = (u64)(*(u32*)&h0) | ((u64)(*(u32*)&h1) << 32);
            *(u64*)(sm + A_LO + off) = (u64)(*(u32*)&l0) | ((u64)(*(u32*)&l1) << 32);
        }
        __syncthreads();                 // A ready, XF32 free

        if (ck + 1 < NCH) ldx(ck + 1);   // refill XF32 under HMMA+scan

        // ---- HMMA: warp w -> cols w*32..+31; rows 64 in 4 m16 groups ----
        #pragma unroll
        for (int gh = 0; gh < 4; ++gh) {
            float acc[4][4];
            #pragma unroll
            for (int nt = 0; nt < 4; ++nt)
                #pragma unroll
                for (int q = 0; q < 4; ++q) acc[nt][q] = 0.f;

            #pragma unroll
            for (int s = 0; s < 4; ++s) {
                u32 ah[4], al[4];
                u32 aoff = swz((u32)((gh * 16 + arow_l) * 128 + s * 32 + acol_l));
                ldsm4(ah[0], ah[1], ah[2], ah[3], sb + A_HI + aoff);
                ldsm4(al[0], al[1], al[2], al[3], sb + A_LO + aoff);
                #pragma unroll
                for (int np = 0; np < 2; ++np) {
                    u32 bh[4], bl[4];
                    u32 boff = swz((u32)((w * 32 + np * 16 + brow_l) * 128 + s * 32 + bcol_l));
                    ldsm4(bh[0], bh[1], bh[2], bh[3], sb + W_HI + boff);
                    ldsm4(bl[0], bl[1], bl[2], bl[3], sb + W_LO + boff);
                    #pragma unroll
                    for (int nh = 0; nh < 2; ++nh) {
                        float* a5 = acc[np * 2 + nh];
                        mma16816(a5, ah, bh[nh * 2], bh[nh * 2 + 1]);
                        mma16816(a5, al, bh[nh * 2], bh[nh * 2 + 1]);
                        mma16816(a5, ah, bl[nh * 2], bl[nh * 2 + 1]);
                    }
                }
            }
            // epilogue: +bias -> proj smem (padded rows)
            int r0 = gh * 16 + (lane >> 2);
            #pragma unroll
            for (int nt = 0; nt < 4; ++nt) {
                int col = w * 32 + nt * 8 + (lane & 3) * 2;
                float b0v = bsm[col], b1v = bsm[col + 1];
                *(float2*)&projf[r0 * PROW + col] =
                    make_float2(acc[nt][0] + b0v, acc[nt][1] + b1v);
                *(float2*)&projf[(r0 + 8) * PROW + col] =
                    make_float2(acc[nt][2] + b0v, acc[nt][3] + b1v);
            }
        }
        __syncthreads();                 // proj ready

        // ---- scan CH steps (warp w = its batch; gates via one LDS.128) ----
        const float* gp = projf + (size_t)w * CH * PROW + lane * 4;
        #pragma unroll
        for (int s = 0; s < CH; ++s) {
            const int buf = s & 1;
            float4 gv = *(const float4*)(gp + s * PROW);   // f,i,o,z of unit=lane

            hshw[buf * 32 + lane] = h;
            __syncwarp();
            const u64* hp = (const u64*)(hshw + buf * 32);

            u64 af = pk2(gv.x, 0.f), ai = pk2(gv.y, 0.f);
            u64 ao = pk2(gv.z, 0.f), az = pk2(gv.w, 0.f);
            #pragma unroll
            for (int k = 0; k < 16; ++k) {
                u64 hh = hp[k];
                fma2(af, Rf[k], hh);
                fma2(ai, Ri[k], hh);
                fma2(ao, Ro[k], hh);
                fma2(az, Rz[k], hh);
            }
            float lo, hi;
            upk2(af, lo, hi); float fT = lo + hi;
            upk2(ai, lo, hi); float iT = lo + hi;
            upk2(ao, lo, hi); float oT = lo + hi;
            upk2(az, lo, hi); float zT = lo + hi;

            float fh = __expf(fminf(fT, 10.f));
            float ih = __expf(fminf(iT, 10.f));
            float rden = __fdividef(1.f, fh + ih + 1e-8f);
            float f  = fh * rden;
            float ii = ih * rden;
            float o  = __fdividef(1.f, 1.f + __expf(-oT));
            float z  = tanh_hw(zT);                    // MUFU.TANH
            cst = f * cst + ii * z;
            nst = f * nst + ii;
            h = o * __fdividef(cst, nst + 1e-8f);
        }
    }

    // ---- head: tanh(fc_w . [h, emb[ticker]] + fc_b) ----
    const int* p32 = (const int*)tick;
    bool is64 = ((p32[1] | p32[3] | p32[5] | p32[7] |
                  p32[9] | p32[11] | p32[13] | p32[15]) == 0);
    long long id = is64 ? ((const long long*)tick)[batch] : (long long)p32[batch];
    float v = fcw[lane] * h;
    if (lane < 8) v += fcw[32 + lane] * emb[id * 8 + lane];
    #pragma unroll
    for (int off = 16; off; off >>= 1)
        v += __shfl_xor_sync(0xffffffffu, v, off);
    if (lane == 0) out[batch] = tanhf(v + fcb[0]);
}

// =====================================================================
extern "C" void kernel_launch(void* const* d_in, const int* in_sizes, int n_in,
                              void* d_out, int out_size) {
    const float* x   = (const float*)d_in[0];
    const void*  tid = d_in[1];
    const float* wf  = (const float*)d_in[2];
    const float* wfb = (const float*)d_in[3];
    const float* wi  = (const float*)d_in[4];
    const float* wib = (const float*)d_in[5];
    const float* wo  = (const float*)d_in[6];
    const float* wob = (const float*)d_in[7];
    const float* wz  = (const float*)d_in[8];
    const float* wzb = (const float*)d_in[9];
    const float* rf  = (const float*)d_in[10];
    const float* ri  = (const float*)d_in[11];
    const float* ro  = (const float*)d_in[12];
    const float* rz  = (const float*)d_in[13];
    const float* emb = (const float*)d_in[14];
    const float* fcw = (const float*)d_in[15];
    const float* fcb = (const float*)d_in[16];
    float* out = (float*)d_out;

    cudaFuncSetAttribute(fused_kernel,
                         cudaFuncAttributeMaxDynamicSharedMemorySize, SM_TOT);

    fused_kernel<<<BB / NB, 128, SM_TOT>>>(
        x, wf, wfb, wi, wib, wo, wob, wz, wzb,
        rf, ri, ro, rz, tid, emb, fcw, fcb, out);
}